// round 7
// baseline (speedup 1.0000x reference)
#include <cuda_runtime.h>
#include <cstdint>

// Problem constants
#define B_      4
#define N_      4096
#define DIM_    512
#define H_      8
#define DH_     64
#define M_      256
#define BH_     32          // B_*H_
#define ITERS_  6
#define KC_     33
#define FSPL_   4           // flash3 KV splits

// ------------------------- scratch (device globals) -------------------------
__device__ float g_xn  [B_ * N_ * DIM_];
__device__ float g_q   [BH_ * N_ * DH_];
__device__ float g_k   [BH_ * N_ * DH_];
__device__ float g_v   [BH_ * N_ * DH_];
__device__ float g_ql  [BH_ * M_ * DH_];
__device__ float g_kl  [BH_ * M_ * DH_];
__device__ float g_a2  [BH_ * M_ * M_];
__device__ float g_zA  [BH_ * M_ * M_];
__device__ float g_zB  [BH_ * M_ * M_];
__device__ float g_xz  [BH_ * M_ * M_];
__device__ float g_t1  [BH_ * M_ * M_];
__device__ float g_t2  [BH_ * M_ * M_];
__device__ float g_po  [BH_ * FSPL_ * M_ * DH_];
__device__ float g_pml [BH_ * FSPL_ * M_ * 2];
__device__ float g_a3v [BH_ * M_ * DH_];
__device__ float g_zv  [BH_ * M_ * DH_];
__device__ float g_oat [BH_ * N_ * DH_];
__device__ float g_outc[B_ * N_ * DIM_];
__device__ unsigned g_max;

// ------------------------- reductions -------------------------
__device__ __forceinline__ float warpSum(float v) {
#pragma unroll
    for (int o = 16; o > 0; o >>= 1) v += __shfl_xor_sync(0xffffffffu, v, o);
    return v;
}
__device__ __forceinline__ float warpMax(float v) {
#pragma unroll
    for (int o = 16; o > 0; o >>= 1) v = fmaxf(v, __shfl_xor_sync(0xffffffffu, v, o));
    return v;
}
__device__ __forceinline__ float blockSum(float v, float* sh, int nw) {
    int l = threadIdx.x & 31, w = threadIdx.x >> 5;
    v = warpSum(v);
    if (l == 0) sh[w] = v;
    __syncthreads();
    if (w == 0) {
        float x = (l < nw) ? sh[l] : 0.f;
        x = warpSum(x);
        if (l == 0) sh[0] = x;
    }
    __syncthreads();
    float r = sh[0];
    __syncthreads();
    return r;
}
__device__ __forceinline__ float blockMax(float v, float* sh, int nw) {
    int l = threadIdx.x & 31, w = threadIdx.x >> 5;
    v = warpMax(v);
    if (l == 0) sh[w] = v;
    __syncthreads();
    if (w == 0) {
        float x = (l < nw) ? sh[l] : -3.4e38f;
        x = warpMax(x);
        if (l == 0) sh[0] = x;
    }
    __syncthreads();
    float r = sh[0];
    __syncthreads();
    return r;
}

// ------------------------- tf32 helpers -------------------------
__device__ __forceinline__ float f2tf(float x) {
    uint32_t r;
    asm("cvt.rna.tf32.f32 %0, %1;" : "=r"(r) : "f"(x));
    return __uint_as_float(r);
}
__device__ __forceinline__ float4 f2tf4(float4 v) {
    return make_float4(f2tf(v.x), f2tf(v.y), f2tf(v.z), f2tf(v.w));
}
__device__ __forceinline__ void mma8(float* d, const uint32_t* a, const uint32_t* b) {
    asm volatile(
        "mma.sync.aligned.m16n8k8.row.col.f32.tf32.tf32.f32 "
        "{%0,%1,%2,%3}, {%4,%5,%6,%7}, {%8,%9}, {%0,%1,%2,%3};\n"
        : "+f"(d[0]), "+f"(d[1]), "+f"(d[2]), "+f"(d[3])
        : "r"(a[0]), "r"(a[1]), "r"(a[2]), "r"(a[3]), "r"(b[0]), "r"(b[1]));
}

// ------------------------- layernorm -------------------------
__global__ void ln_kernel(const float* __restrict__ x, const float* __restrict__ w,
                          const float* __restrict__ b, float* __restrict__ xn) {
    __shared__ float sh[8];
    long long row = blockIdx.x;
    const float4* p = (const float4*)(x + row * DIM_);
    float4 v = p[threadIdx.x];                       // 128 threads * 4
    float s  = v.x + v.y + v.z + v.w;
    float sq = v.x * v.x + v.y * v.y + v.z * v.z + v.w * v.w;
    s  = blockSum(s,  sh, 4);
    sq = blockSum(sq, sh, 4);
    float mean = s * (1.f / DIM_);
    float var  = sq * (1.f / DIM_) - mean * mean;
    float rstd = rsqrtf(var + 1e-5f);
    float4 wv = ((const float4*)w)[threadIdx.x];
    float4 bv = ((const float4*)b)[threadIdx.x];
    float4 o;
    o.x = (v.x - mean) * rstd * wv.x + bv.x;
    o.y = (v.y - mean) * rstd * wv.y + bv.y;
    o.z = (v.z - mean) * rstd * wv.z + bv.z;
    o.w = (v.w - mean) * rstd * wv.w + bv.w;
    ((float4*)(xn + row * DIM_))[threadIdx.x] = o;
}

// ------------------------- tf32 tensor-core GEMM -------------------------
// C = alpha*(A @ opB) + beta*A   (beta path used by square pinv GEMMs)
// EPI 0: standard.  EPI 1: qkv scatter into q/k/v.  EPI 2: += x + b_out.
template<int BM, int BN, int WRS, int EPI, bool TRANSB>
__global__ __launch_bounds__(256) void mma_gemm(
    const float* __restrict__ A, const float* __restrict__ B, float* __restrict__ C,
    int Kper, int lda, int ldb, int ldc,
    long long sA, long long sB, long long sC,
    float alpha, float beta,
    const float* __restrict__ E1, const float* __restrict__ E2,
    float* __restrict__ O1, float* __restrict__ O2, float* __restrict__ O3)
{
    constexpr int BK  = 16;
    constexpr int WCS = 8 / WRS;
    constexpr int WM  = BM / WRS;
    constexpr int WN  = BN / WCS;
    constexpr int FM  = WM / 16;
    constexpr int FN  = WN / 8;
    constexpr int SKA = BK + 4;
    constexpr int SNB = BN + 8;
    constexpr int AREP = BM / 64;
    constexpr int BREP = BN / 64;

    __shared__ float As[2][BM][SKA];   // [m][k]
    __shared__ float Bs[2][BK][SNB];   // [k][n]

    const int bz = blockIdx.z;
    A += bz * sA;
    B += bz * sB;
    if (C) C += bz * sC;

    const int i0 = blockIdx.y * BM, j0 = blockIdx.x * BN;
    const int tid  = threadIdx.x;
    const int lane = tid & 31, g = lane >> 2, tig = lane & 3;
    const int wid  = tid >> 5;
    const int wm   = (wid / WCS) * WM;
    const int wn   = (wid % WCS) * WN;

    const int arow = tid >> 2, ac4 = (tid & 3) << 2;
    const int bnn4 = BN / 4;
    const int bk0  = tid / bnn4, bn4 = (tid % bnn4) << 2;
    const int bkstep = 1024 / BN;

    const float* Aptr = &A[(long long)(i0 + arow) * lda + ac4];
    const float* Bptr = TRANSB ? &B[(long long)(j0 + arow) * ldb + ac4]
                               : &B[(long long)bk0 * ldb + j0 + bn4];

    float acc[FM][FN][4] = {};
    const int nt = Kper / BK;

    float4 stA[AREP], stB[BREP];

#pragma unroll
    for (int r = 0; r < AREP; r++) stA[r] = *(const float4*)(Aptr + (long long)r * 64 * lda);
#pragma unroll
    for (int r = 0; r < BREP; r++)
        stB[r] = TRANSB ? *(const float4*)(Bptr + (long long)r * 64 * ldb)
                        : *(const float4*)(Bptr + (long long)r * bkstep * ldb);
#pragma unroll
    for (int r = 0; r < AREP; r++)
        *(float4*)&As[0][arow + r * 64][ac4] = f2tf4(stA[r]);
#pragma unroll
    for (int r = 0; r < BREP; r++) {
        float4 bv = f2tf4(stB[r]);
        if (TRANSB) {
            Bs[0][ac4 + 0][arow + r * 64] = bv.x; Bs[0][ac4 + 1][arow + r * 64] = bv.y;
            Bs[0][ac4 + 2][arow + r * 64] = bv.z; Bs[0][ac4 + 3][arow + r * 64] = bv.w;
        } else {
            *(float4*)&Bs[0][bk0 + r * bkstep][bn4] = bv;
        }
    }
    __syncthreads();

    for (int t = 0; t < nt; t++) {
        const int cur = t & 1, nb = cur ^ 1;
        if (t + 1 < nt) {
            const long long ko = (long long)(t + 1) * BK;
#pragma unroll
            for (int r = 0; r < AREP; r++)
                stA[r] = *(const float4*)(Aptr + (long long)r * 64 * lda + ko);
#pragma unroll
            for (int r = 0; r < BREP; r++)
                stB[r] = TRANSB ? *(const float4*)(Bptr + (long long)r * 64 * ldb + ko)
                                : *(const float4*)(Bptr + ((long long)r * bkstep + ko) * ldb);
        }
#pragma unroll
        for (int ks = 0; ks < 2; ks++) {
            const int kb = ks * 8;
            uint32_t af[FM][4], bf[FN][2];
#pragma unroll
            for (int mi = 0; mi < FM; mi++) {
                const int row = wm + mi * 16 + g;
                af[mi][0] = __float_as_uint(As[cur][row    ][kb + tig]);
                af[mi][1] = __float_as_uint(As[cur][row + 8][kb + tig]);
                af[mi][2] = __float_as_uint(As[cur][row    ][kb + tig + 4]);
                af[mi][3] = __float_as_uint(As[cur][row + 8][kb + tig + 4]);
            }
#pragma unroll
            for (int ni = 0; ni < FN; ni++) {
                const int col = wn + ni * 8 + g;
                bf[ni][0] = __float_as_uint(Bs[cur][kb + tig    ][col]);
                bf[ni][1] = __float_as_uint(Bs[cur][kb + tig + 4][col]);
            }
#pragma unroll
            for (int mi = 0; mi < FM; mi++)
#pragma unroll
                for (int ni = 0; ni < FN; ni++) mma8(acc[mi][ni], af[mi], bf[ni]);
        }
        if (t + 1 < nt) {
#pragma unroll
            for (int r = 0; r < AREP; r++)
                *(float4*)&As[nb][arow + r * 64][ac4] = f2tf4(stA[r]);
#pragma unroll
            for (int r = 0; r < BREP; r++) {
                float4 bv = f2tf4(stB[r]);
                if (TRANSB) {
                    Bs[nb][ac4 + 0][arow + r * 64] = bv.x; Bs[nb][ac4 + 1][arow + r * 64] = bv.y;
                    Bs[nb][ac4 + 2][arow + r * 64] = bv.z; Bs[nb][ac4 + 3][arow + r * 64] = bv.w;
                } else {
                    *(float4*)&Bs[nb][bk0 + r * bkstep][bn4] = bv;
                }
            }
        }
        __syncthreads();
    }

#pragma unroll
    for (int mi = 0; mi < FM; mi++) {
        const int r0 = i0 + wm + mi * 16 + g;
        const int r1 = r0 + 8;
#pragma unroll
        for (int ni = 0; ni < FN; ni++) {
            const int c0 = j0 + wn + ni * 8 + 2 * tig;
            const float* d = acc[mi][ni];
            if (EPI == 0) {
                float2 v0 = make_float2(alpha * d[0], alpha * d[1]);
                float2 v1 = make_float2(alpha * d[2], alpha * d[3]);
                if (beta != 0.f) {
                    float2 e0 = *(const float2*)&A[(long long)r0 * lda + c0];
                    float2 e1 = *(const float2*)&A[(long long)r1 * lda + c0];
                    v0.x += beta * e0.x; v0.y += beta * e0.y;
                    v1.x += beta * e1.x; v1.y += beta * e1.y;
                }
                *(float2*)&C[(long long)r0 * ldc + c0] = v0;
                *(float2*)&C[(long long)r1 * ldc + c0] = v1;
            } else if (EPI == 1) {
                const int sec = c0 >> 9, rem = c0 & 511;
                const int h = rem >> 6, dd = rem & 63;
#pragma unroll
                for (int half = 0; half < 2; half++) {
                    const int r = half ? r1 : r0;
                    const int bb_ = r >> 12, nn_ = r & 4095;
                    const long long di = (((long long)(bb_ * H_ + h)) * N_ + nn_) * DH_ + dd;
                    float2 v = half ? make_float2(d[2], d[3]) : make_float2(d[0], d[1]);
                    if (sec == 0) { v.x *= 0.125f; v.y *= 0.125f; *(float2*)&O1[di] = v; }
                    else if (sec == 1) *(float2*)&O2[di] = v;
                    else               *(float2*)&O3[di] = v;
                }
            } else { // EPI == 2
                const long long d0i = (long long)r0 * DIM_ + c0;
                const long long d1i = (long long)r1 * DIM_ + c0;
                float2 e0 = *(const float2*)&E1[d0i];
                float2 e1 = *(const float2*)&E1[d1i];
                float2 b2 = *(const float2*)&E2[c0];
                *(float2*)&C[d0i] = make_float2(d[0] + e0.x + b2.x, d[1] + e0.y + b2.y);
                *(float2*)&C[d1i] = make_float2(d[2] + e1.x + b2.x, d[3] + e1.y + b2.y);
            }
        }
    }
}

// ------------------------- flash attention: O = softmax(Q@K^T) @ V -------------------
// Q: [bh, R, 64] (R = gridDim.x*64), K,V: [bh, C, 64].
// splits == 1: writes normalized O [bh, R, 64].
// splits  > 1: blockIdx.z = sp covers C/splits KV cols; writes unnormalized
//              partial O at [(bh*splits+sp), R, 64] and (m,l) into PML.
// 128 threads = 4 warps; each warp owns 16 rows; BC = 128 per chunk.
// Dynamic smem: Qs[64][68] | KP union(Ks[128][68], Ps[64][140]) | Vs[128][68].
#define FL_QS   0
#define FL_KP   (64 * 68)
#define FL_VS   (64 * 68 + 8960)
#define FL_SMEM ((64 * 68 + 8960 + 128 * 68) * 4)

__global__ __launch_bounds__(128) void flash_kernel(
    const float* __restrict__ Q, const float* __restrict__ K,
    const float* __restrict__ V, float* __restrict__ O,
    float* __restrict__ PML, int C, int splits)
{
    extern __shared__ float sm[];
    float* Qs = sm + FL_QS;
    float* KP = sm + FL_KP;
    float* Vs = sm + FL_VS;

    const int bh = blockIdx.y;
    const int sp = blockIdx.z;
    const int R  = gridDim.x * 64;
    const int Cper = C / splits;
    const long long qoff = ((long long)bh * R + blockIdx.x * 64) * 64;
    Q += qoff;
    K += ((long long)bh * C + (long long)sp * Cper) * 64;
    V += ((long long)bh * C + (long long)sp * Cper) * 64;

    const int tid = threadIdx.x;
    const int lane = tid & 31, g = lane >> 2, tig = lane & 3;
    const int w = tid >> 5;
    const int r0l = w * 16 + g, r1l = r0l + 8;

    // load Q block (64x64)
#pragma unroll
    for (int i = 0; i < 8; i++) {
        int idx = tid + i * 128;
        int row = idx >> 4, c4 = (idx & 15) << 2;
        *(float4*)&Qs[row * 68 + c4] = f2tf4(*(const float4*)&Q[row * 64 + c4]);
    }

    float o[8][4] = {};
    float m0 = -1e30f, m1 = -1e30f, l0 = 0.f, l1 = 0.f;

    for (int c0 = 0; c0 < Cper; c0 += 128) {
        __syncthreads();
        // load K,V chunk (128x64 each)
#pragma unroll
        for (int i = 0; i < 16; i++) {
            int idx = tid + i * 128;
            int row = idx >> 4, c4 = (idx & 15) << 2;
            *(float4*)&KP[row * 68 + c4] = f2tf4(*(const float4*)&K[(long long)(c0 + row) * 64 + c4]);
            *(float4*)&Vs[row * 68 + c4] = f2tf4(*(const float4*)&V[(long long)(c0 + row) * 64 + c4]);
        }
        __syncthreads();

        // S = Q @ K^T  (16 rows x 128 cols per warp)
        float s[16][4] = {};
#pragma unroll
        for (int kb = 0; kb < 64; kb += 8) {
            uint32_t af[4];
            af[0] = __float_as_uint(Qs[r0l * 68 + kb + tig]);
            af[1] = __float_as_uint(Qs[r1l * 68 + kb + tig]);
            af[2] = __float_as_uint(Qs[r0l * 68 + kb + tig + 4]);
            af[3] = __float_as_uint(Qs[r1l * 68 + kb + tig + 4]);
#pragma unroll
            for (int ni = 0; ni < 16; ni++) {
                uint32_t bf[2];
                bf[0] = __float_as_uint(KP[(ni * 8 + g) * 68 + kb + tig]);
                bf[1] = __float_as_uint(KP[(ni * 8 + g) * 68 + kb + tig + 4]);
                mma8(s[ni], af, bf);
            }
        }

        // online softmax
        float cm0 = -1e30f, cm1 = -1e30f;
#pragma unroll
        for (int ni = 0; ni < 16; ni++) {
            cm0 = fmaxf(cm0, fmaxf(s[ni][0], s[ni][1]));
            cm1 = fmaxf(cm1, fmaxf(s[ni][2], s[ni][3]));
        }
        cm0 = fmaxf(cm0, __shfl_xor_sync(0xffffffffu, cm0, 1));
        cm0 = fmaxf(cm0, __shfl_xor_sync(0xffffffffu, cm0, 2));
        cm1 = fmaxf(cm1, __shfl_xor_sync(0xffffffffu, cm1, 1));
        cm1 = fmaxf(cm1, __shfl_xor_sync(0xffffffffu, cm1, 2));
        float M0 = fmaxf(m0, cm0), M1 = fmaxf(m1, cm1);
        float corr0 = __expf(m0 - M0), corr1 = __expf(m1 - M1);
        float sum0 = 0.f, sum1 = 0.f;
#pragma unroll
        for (int ni = 0; ni < 16; ni++) {
            s[ni][0] = __expf(s[ni][0] - M0);
            s[ni][1] = __expf(s[ni][1] - M0);
            s[ni][2] = __expf(s[ni][2] - M1);
            s[ni][3] = __expf(s[ni][3] - M1);
            sum0 += s[ni][0] + s[ni][1];
            sum1 += s[ni][2] + s[ni][3];
        }
        sum0 += __shfl_xor_sync(0xffffffffu, sum0, 1);
        sum0 += __shfl_xor_sync(0xffffffffu, sum0, 2);
        sum1 += __shfl_xor_sync(0xffffffffu, sum1, 1);
        sum1 += __shfl_xor_sync(0xffffffffu, sum1, 2);
        l0 = l0 * corr0 + sum0;
        l1 = l1 * corr1 + sum1;
        m0 = M0; m1 = M1;
#pragma unroll
        for (int ni = 0; ni < 8; ni++) {
            o[ni][0] *= corr0; o[ni][1] *= corr0;
            o[ni][2] *= corr1; o[ni][3] *= corr1;
        }

        __syncthreads();      // all warps done reading K tile (Ps aliases it)
        // write P (tf32) to Ps[64][140]
#pragma unroll
        for (int ni = 0; ni < 16; ni++) {
            int col = ni * 8 + 2 * tig;
            *(float2*)&KP[r0l * 140 + col] = make_float2(f2tf(s[ni][0]), f2tf(s[ni][1]));
            *(float2*)&KP[r1l * 140 + col] = make_float2(f2tf(s[ni][2]), f2tf(s[ni][3]));
        }
        __syncthreads();

        // O += P @ V   (K = 128)
#pragma unroll
        for (int kb = 0; kb < 128; kb += 8) {
            uint32_t af[4];
            af[0] = __float_as_uint(KP[r0l * 140 + kb + tig]);
            af[1] = __float_as_uint(KP[r1l * 140 + kb + tig]);
            af[2] = __float_as_uint(KP[r0l * 140 + kb + tig + 4]);
            af[3] = __float_as_uint(KP[r1l * 140 + kb + tig + 4]);
#pragma unroll
            for (int ni = 0; ni < 8; ni++) {
                uint32_t bf[2];
                bf[0] = __float_as_uint(Vs[(kb + tig) * 68 + ni * 8 + g]);
                bf[1] = __float_as_uint(Vs[(kb + tig + 4) * 68 + ni * 8 + g]);
                mma8(o[ni], af, bf);
            }
        }
    }

    if (splits == 1) {
        float* Op = O + qoff;
        const float inv0 = 1.f / l0, inv1 = 1.f / l1;
#pragma unroll
        for (int ni = 0; ni < 8; ni++) {
            int col = ni * 8 + 2 * tig;
            *(float2*)&Op[r0l * 64 + col] = make_float2(o[ni][0] * inv0, o[ni][1] * inv0);
            *(float2*)&Op[r1l * 64 + col] = make_float2(o[ni][2] * inv1, o[ni][3] * inv1);
        }
    } else {
        const long long pbase = ((long long)(bh * splits + sp) * R + blockIdx.x * 64);
        float* Op = O + pbase * 64;
#pragma unroll
        for (int ni = 0; ni < 8; ni++) {
            int col = ni * 8 + 2 * tig;
            *(float2*)&Op[r0l * 64 + col] = make_float2(o[ni][0], o[ni][1]);
            *(float2*)&Op[r1l * 64 + col] = make_float2(o[ni][2], o[ni][3]);
        }
        if (tig == 0) {
            PML[(pbase + r0l) * 2 + 0] = m0;
            PML[(pbase + r0l) * 2 + 1] = l0;
            PML[(pbase + r1l) * 2 + 0] = m1;
            PML[(pbase + r1l) * 2 + 1] = l1;
        }
    }
}

// ------------------------- flash split merge -------------------------
__global__ void flash_merge_kernel(const float* __restrict__ po,
                                   const float* __restrict__ pml,
                                   float* __restrict__ outp) {
    int idx = blockIdx.x * 256 + threadIdx.x;       // BH_*M_*DH_
    int col = idx & 63;
    int row = (idx >> 6) & 255;
    int bh  = idx >> 14;
    float m[FSPL_], l[FSPL_];
    float M = -1e30f;
#pragma unroll
    for (int s = 0; s < FSPL_; s++) {
        long long b = (long long)(bh * FSPL_ + s) * M_ + row;
        m[s] = pml[b * 2]; l[s] = pml[b * 2 + 1];
        M = fmaxf(M, m[s]);
    }
    float acc = 0.f, lt = 0.f;
#pragma unroll
    for (int s = 0; s < FSPL_; s++) {
        float w = __expf(m[s] - M);
        lt += l[s] * w;
        acc += po[(((long long)(bh * FSPL_ + s) * M_ + row) << 6) + col] * w;
    }
    outp[(((long long)bh * M_ + row) << 6) + col] = acc / lt;
}

// ------------------------- landmarks (mean over 16 tokens) -------------------------
__global__ void landmark_kernel(const float* __restrict__ q, const float* __restrict__ k,
                                float* __restrict__ ql, float* __restrict__ kl) {
    int idx = blockIdx.x * 256 + threadIdx.x;      // BH_*M_*DH_ = 524288
    int d = idx & 63;
    int m = (idx >> 6) & 255;
    int bh = idx >> 14;
    long long base = ((long long)bh * N_ + m * 16) * DH_ + d;
    float sq = 0.f, sk = 0.f;
#pragma unroll
    for (int j = 0; j < 16; j++) {
        sq += q[base + (long long)j * DH_];
        sk += k[base + (long long)j * DH_];
    }
    ql[idx] = sq * (1.f / 16.f);
    kl[idx] = sk * (1.f / 16.f);
}

// ------------------------- softmax over last dim (a2 only) -------------------------
__global__ void softmax_kernel(float* __restrict__ p) {
    __shared__ float sh[8];
    float* r = p + (long long)blockIdx.x * 256;
    float v = r[threadIdx.x];
    float mx = blockMax(v, sh, 8);
    float e = expf(v - mx);
    float s = blockSum(e, sh, 8);
    r[threadIdx.x] = e / s;
}

// ------------------------- pinv init helpers -------------------------
// a2 rows are softmax outputs: row sums == 1, so max(col-sums-over-last-dim) == 1.
// Only the max over column sums (sum over dim -2) is needed.
__global__ void init_max_kernel() {
    if (threadIdx.x == 0) g_max = 0u;
}
__global__ void colsum_max_kernel(const float* __restrict__ a2) {
    __shared__ float sh[8];
    int bh = blockIdx.x >> 8, j = blockIdx.x & 255;
    float v = fabsf(a2[(long long)bh * M_ * M_ + (long long)threadIdx.x * M_ + j]);
    float s = blockSum(v, sh, 8);
    if (threadIdx.x == 0) atomicMax(&g_max, __float_as_uint(s));
}
__global__ void zinit_kernel(const float* __restrict__ a2, float* __restrict__ z) {
    int idx = blockIdx.x * 256 + threadIdx.x;       // BH_*M_*M_
    int j = idx & 255, i = (idx >> 8) & 255, bh = idx >> 16;
    float scale = 1.f / __uint_as_float(g_max);
    z[idx] = a2[(long long)bh * M_ * M_ + (long long)j * M_ + i] * scale;
}

// ------------------------- tiled depthwise conv + merge heads -------------------------
#define VSTR 68
__global__ __launch_bounds__(256) void conv_merge_kernel(
    const float* __restrict__ v, const float* __restrict__ oat,
    const float* __restrict__ wconv, float* __restrict__ outc)
{
    __shared__ float vt[160 * VSTR];
    __shared__ float wc[KC_];
    const int bh = blockIdx.y, h = bh & 7, b = bh >> 3;
    const int n0 = blockIdx.x * 128;
    const int tid = threadIdx.x;
    if (tid < KC_) wc[tid] = wconv[h * KC_ + tid];
    const float* vb = v + (long long)bh * N_ * DH_;
#pragma unroll
    for (int i = 0; i < 10; i++) {
        int idx = tid + i * 256;                    // 2560 float4 slots = 160 rows x 16
        int row = idx >> 4, c4 = (idx & 15) << 2;
        int gn = n0 - 16 + row;
        float4 val = make_float4(0.f, 0.f, 0.f, 0.f);
        if (gn >= 0 && gn < N_) val = *(const float4*)&vb[(long long)gn * DH_ + c4];
        *(float4*)&vt[row * VSTR + c4] = val;
    }
    __syncthreads();
    const float* ob = oat + (long long)bh * N_ * DH_;
    float* outb = outc + ((long long)b * N_ + n0) * DIM_ + h * DH_;
#pragma unroll 4
    for (int i = 0; i < 32; i++) {
        int idx = tid + i * 256;
        int nl = idx >> 6, d = idx & 63;
        float r = 0.f;
#pragma unroll
        for (int kk = 0; kk < KC_; kk++) r = fmaf(vt[(nl + kk) * VSTR + d], wc[kk], r);
        outb[(long long)nl * DIM_ + d] = ob[(long long)(n0 + nl) * DH_ + d] + r;
    }
}

// ------------------------- host launcher -------------------------
extern "C" void kernel_launch(void* const* d_in, const int* in_sizes, int n_in,
                              void* d_out, int out_size) {
    const float* x      = (const float*)d_in[0];
    const float* ln_w   = (const float*)d_in[1];
    const float* ln_b   = (const float*)d_in[2];
    const float* w_qkv  = (const float*)d_in[3];
    const float* w_out  = (const float*)d_in[4];
    const float* b_out  = (const float*)d_in[5];
    const float* w_conv = (const float*)d_in[6];
    float* out = (float*)d_out;

    float *p_xn, *p_q, *p_k, *p_v, *p_ql, *p_kl, *p_a2;
    float *p_zA, *p_zB, *p_xz, *p_t1, *p_t2, *p_po, *p_pml, *p_a3v, *p_zv, *p_oat, *p_outc;
    cudaGetSymbolAddress((void**)&p_xn,  g_xn);
    cudaGetSymbolAddress((void**)&p_q,   g_q);
    cudaGetSymbolAddress((void**)&p_k,   g_k);
    cudaGetSymbolAddress((void**)&p_v,   g_v);
    cudaGetSymbolAddress((void**)&p_ql,  g_ql);
    cudaGetSymbolAddress((void**)&p_kl,  g_kl);
    cudaGetSymbolAddress((void**)&p_a2,  g_a2);
    cudaGetSymbolAddress((void**)&p_zA,  g_zA);
    cudaGetSymbolAddress((void**)&p_zB,  g_zB);
    cudaGetSymbolAddress((void**)&p_xz,  g_xz);
    cudaGetSymbolAddress((void**)&p_t1,  g_t1);
    cudaGetSymbolAddress((void**)&p_t2,  g_t2);
    cudaGetSymbolAddress((void**)&p_po,  g_po);
    cudaGetSymbolAddress((void**)&p_pml, g_pml);
    cudaGetSymbolAddress((void**)&p_a3v, g_a3v);
    cudaGetSymbolAddress((void**)&p_zv,  g_zv);
    cudaGetSymbolAddress((void**)&p_oat, g_oat);
    cudaGetSymbolAddress((void**)&p_outc,g_outc);

    static int flash_attr_set = 0;
    if (!flash_attr_set) {
        cudaFuncSetAttribute(flash_kernel, cudaFuncAttributeMaxDynamicSharedMemorySize, FL_SMEM);
        flash_attr_set = 1;
    }

    const long long sL  = (long long)M_ * DH_;      // 16384
    const long long sM2 = (long long)M_ * M_;       // 65536

    // 1. LayerNorm
    ln_kernel<<<B_ * N_, 128>>>(x, ln_w, ln_b, p_xn);

    // 2. QKV GEMM [16384,512] @ [512,1536] -> scatter into q/k/v [bh,n,dh]
    mma_gemm<128, 128, 2, 1, false><<<dim3(12, 128, 1), 256>>>(
        p_xn, w_qkv, nullptr, 512, 512, 1536, 0, 0, 0, 0, 1.f, 0.f,
        nullptr, nullptr, p_q, p_k, p_v);

    // 3. Landmarks (mean over 16 tokens)
    landmark_kernel<<<(BH_ * M_ * DH_) / 256, 256>>>(p_q, p_k, p_ql, p_kl);

    // 4. sim2 = ql @ kl^T [256,256] + softmax
    mma_gemm<128, 128, 2, 0, true><<<dim3(2, 2, BH_), 256>>>(
        p_ql, p_kl, p_a2, 64, 64, 64, 256, sL, sL, sM2, 1.f, 0.f,
        nullptr, nullptr, nullptr, nullptr, nullptr);
    softmax_kernel<<<BH_ * M_, 256>>>(p_a2);

    // 5. flash3 (split-KV x4): a3v = softmax(ql @ k^T) @ v   [bh,256,64]
    flash_kernel<<<dim3(M_ / 64, BH_, FSPL_), 128, FL_SMEM>>>(
        p_ql, p_k, p_v, p_po, p_pml, N_, FSPL_);
    flash_merge_kernel<<<(BH_ * M_ * DH_) / 256, 256>>>(p_po, p_pml, p_a3v);

    // 6. pinv init (maxc == 1 since a2 rows are softmaxed)
    init_max_kernel<<<1, 32>>>();
    colsum_max_kernel<<<BH_ * M_, 256>>>(p_a2);
    zinit_kernel<<<(BH_ * M_ * M_) / 256, 256>>>(p_a2, p_zA);

    // 7. Newton-Schulz iterations (batched 256^3 GEMMs, 32 matrices, 64x64 tiles)
    float* cur = p_zA;
    float* nxt = p_zB;
    for (int it = 0; it < ITERS_; it++) {
        mma_gemm<64, 64, 4, 0, false><<<dim3(4, 4, BH_), 256>>>(
            p_a2, cur, p_xz, 256, 256, 256, 256, sM2, sM2, sM2, 1.f, 0.f,
            nullptr, nullptr, nullptr, nullptr, nullptr);
        mma_gemm<64, 64, 4, 0, false><<<dim3(4, 4, BH_), 256>>>(
            p_xz, p_xz, p_t1, 256, 256, 256, 256, sM2, sM2, sM2, -1.f, 7.f,
            nullptr, nullptr, nullptr, nullptr, nullptr);
        mma_gemm<64, 64, 4, 0, false><<<dim3(4, 4, BH_), 256>>>(
            p_xz, p_t1, p_t2, 256, 256, 256, 256, sM2, sM2, sM2, -1.f, 15.f,
            nullptr, nullptr, nullptr, nullptr, nullptr);
        mma_gemm<64, 64, 4, 0, false><<<dim3(4, 4, BH_), 256>>>(
            cur, p_t2, nxt, 256, 256, 256, 256, sM2, sM2, sM2, -0.25f, 3.25f,
            nullptr, nullptr, nullptr, nullptr, nullptr);
        float* tmp = cur; cur = nxt; nxt = tmp;
    }

    // 8. zv = a2inv @ a3v  [256,64]
    mma_gemm<64, 64, 4, 0, false><<<dim3(1, 4, BH_), 256>>>(
        cur, p_a3v, p_zv, 256, 256, 64, 64, sM2, sL, sL, 1.f, 0.f,
        nullptr, nullptr, nullptr, nullptr, nullptr);

    // 9. flash1: oat = softmax(q @ kl^T) @ zv   [bh,4096,64]
    flash_kernel<<<dim3(N_ / 64, BH_, 1), 128, FL_SMEM>>>(
        p_q, p_kl, p_zv, p_oat, nullptr, M_, 1);

    // 10. depthwise conv residual + head merge -> [b*n, 512]
    conv_merge_kernel<<<dim3(N_ / 128, BH_), 256>>>(p_v, p_oat, w_conv, p_outc);

    // 11. final: out = x + outc @ w_out + b_out
    mma_gemm<128, 128, 2, 2, false><<<dim3(4, 128, 1), 256>>>(
        p_outc, w_out, out, 512, 512, 512, 512, 0, 0, 0, 1.f, 0.f,
        x, b_out, nullptr, nullptr, nullptr);
}

// round 8
// speedup vs baseline: 1.1243x; 1.1243x over previous
#include <cuda_runtime.h>
#include <cstdint>

// Problem constants
#define B_      4
#define N_      4096
#define DIM_    512
#define H_      8
#define DH_     64
#define M_      256
#define BH_     32          // B_*H_
#define ITERS_  6
#define KC_     33

// ------------------------- scratch (device globals) -------------------------
__device__ float g_xn  [B_ * N_ * DIM_];
__device__ float g_q   [BH_ * N_ * DH_];
__device__ float g_k   [BH_ * N_ * DH_];
__device__ float g_v   [BH_ * N_ * DH_];
__device__ float g_ql  [BH_ * M_ * DH_];
__device__ float g_kl  [BH_ * M_ * DH_];
__device__ float g_a2  [BH_ * M_ * M_];
__device__ float g_zA  [BH_ * M_ * M_];
__device__ float g_zB  [BH_ * M_ * M_];
__device__ float g_xz  [BH_ * M_ * M_];
__device__ float g_t1  [BH_ * M_ * M_];
__device__ float g_t2  [BH_ * M_ * M_];
__device__ float g_a3v [BH_ * M_ * DH_];
__device__ float g_zv  [BH_ * M_ * DH_];
__device__ float g_oat [BH_ * N_ * DH_];
__device__ float g_outc[B_ * N_ * DIM_];
__device__ unsigned g_max;

// ------------------------- reductions -------------------------
__device__ __forceinline__ float warpSum(float v) {
#pragma unroll
    for (int o = 16; o > 0; o >>= 1) v += __shfl_xor_sync(0xffffffffu, v, o);
    return v;
}
__device__ __forceinline__ float warpMax(float v) {
#pragma unroll
    for (int o = 16; o > 0; o >>= 1) v = fmaxf(v, __shfl_xor_sync(0xffffffffu, v, o));
    return v;
}
__device__ __forceinline__ float blockSum(float v, float* sh, int nw) {
    int l = threadIdx.x & 31, w = threadIdx.x >> 5;
    v = warpSum(v);
    if (l == 0) sh[w] = v;
    __syncthreads();
    if (w == 0) {
        float x = (l < nw) ? sh[l] : 0.f;
        x = warpSum(x);
        if (l == 0) sh[0] = x;
    }
    __syncthreads();
    float r = sh[0];
    __syncthreads();
    return r;
}
__device__ __forceinline__ float blockMax(float v, float* sh, int nw) {
    int l = threadIdx.x & 31, w = threadIdx.x >> 5;
    v = warpMax(v);
    if (l == 0) sh[w] = v;
    __syncthreads();
    if (w == 0) {
        float x = (l < nw) ? sh[l] : -3.4e38f;
        x = warpMax(x);
        if (l == 0) sh[0] = x;
    }
    __syncthreads();
    float r = sh[0];
    __syncthreads();
    return r;
}

// ------------------------- tf32 helpers -------------------------
__device__ __forceinline__ float f2tf(float x) {
    uint32_t r;
    asm("cvt.rna.tf32.f32 %0, %1;" : "=r"(r) : "f"(x));
    return __uint_as_float(r);
}
__device__ __forceinline__ float4 f2tf4(float4 v) {
    return make_float4(f2tf(v.x), f2tf(v.y), f2tf(v.z), f2tf(v.w));
}
__device__ __forceinline__ void mma8(float* d, const uint32_t* a, const uint32_t* b) {
    asm volatile(
        "mma.sync.aligned.m16n8k8.row.col.f32.tf32.tf32.f32 "
        "{%0,%1,%2,%3}, {%4,%5,%6,%7}, {%8,%9}, {%0,%1,%2,%3};\n"
        : "+f"(d[0]), "+f"(d[1]), "+f"(d[2]), "+f"(d[3])
        : "r"(a[0]), "r"(a[1]), "r"(a[2]), "r"(a[3]), "r"(b[0]), "r"(b[1]));
}

// ------------------------- layernorm -------------------------
__global__ void ln_kernel(const float* __restrict__ x, const float* __restrict__ w,
                          const float* __restrict__ b, float* __restrict__ xn) {
    __shared__ float sh[8];
    long long row = blockIdx.x;
    const float4* p = (const float4*)(x + row * DIM_);
    float4 v = p[threadIdx.x];                       // 128 threads * 4
    float s  = v.x + v.y + v.z + v.w;
    float sq = v.x * v.x + v.y * v.y + v.z * v.z + v.w * v.w;
    s  = blockSum(s,  sh, 4);
    sq = blockSum(sq, sh, 4);
    float mean = s * (1.f / DIM_);
    float var  = sq * (1.f / DIM_) - mean * mean;
    float rstd = rsqrtf(var + 1e-5f);
    float4 wv = ((const float4*)w)[threadIdx.x];
    float4 bv = ((const float4*)b)[threadIdx.x];
    float4 o;
    o.x = (v.x - mean) * rstd * wv.x + bv.x;
    o.y = (v.y - mean) * rstd * wv.y + bv.y;
    o.z = (v.z - mean) * rstd * wv.z + bv.z;
    o.w = (v.w - mean) * rstd * wv.w + bv.w;
    ((float4*)(xn + row * DIM_))[threadIdx.x] = o;
}

// ------------------------- tf32 tensor-core GEMM -------------------------
// C = alpha*(A @ opB) + beta*A   (beta path used by square pinv GEMMs)
// EPI 0: standard.  EPI 1: qkv scatter into q/k/v.  EPI 2: += x + b_out.
template<int BM, int BN, int WRS, int EPI, bool TRANSB>
__global__ __launch_bounds__(256) void mma_gemm(
    const float* __restrict__ A, const float* __restrict__ B, float* __restrict__ C,
    int Kper, int lda, int ldb, int ldc,
    long long sA, long long sB, long long sC,
    float alpha, float beta,
    const float* __restrict__ E1, const float* __restrict__ E2,
    float* __restrict__ O1, float* __restrict__ O2, float* __restrict__ O3)
{
    constexpr int BK  = 16;
    constexpr int WCS = 8 / WRS;
    constexpr int WM  = BM / WRS;
    constexpr int WN  = BN / WCS;
    constexpr int FM  = WM / 16;
    constexpr int FN  = WN / 8;
    constexpr int SKA = BK + 4;
    constexpr int SNB = BN + 8;
    constexpr int AREP = BM / 64;
    constexpr int BREP = BN / 64;

    __shared__ float As[2][BM][SKA];   // [m][k]
    __shared__ float Bs[2][BK][SNB];   // [k][n]

    const int bz = blockIdx.z;
    A += bz * sA;
    B += bz * sB;
    if (C) C += bz * sC;

    const int i0 = blockIdx.y * BM, j0 = blockIdx.x * BN;
    const int tid  = threadIdx.x;
    const int lane = tid & 31, g = lane >> 2, tig = lane & 3;
    const int wid  = tid >> 5;
    const int wm   = (wid / WCS) * WM;
    const int wn   = (wid % WCS) * WN;

    const int arow = tid >> 2, ac4 = (tid & 3) << 2;
    const int bnn4 = BN / 4;
    const int bk0  = tid / bnn4, bn4 = (tid % bnn4) << 2;
    const int bkstep = 1024 / BN;

    const float* Aptr = &A[(long long)(i0 + arow) * lda + ac4];
    const float* Bptr = TRANSB ? &B[(long long)(j0 + arow) * ldb + ac4]
                               : &B[(long long)bk0 * ldb + j0 + bn4];

    float acc[FM][FN][4] = {};
    const int nt = Kper / BK;

    float4 stA[AREP], stB[BREP];

#pragma unroll
    for (int r = 0; r < AREP; r++) stA[r] = *(const float4*)(Aptr + (long long)r * 64 * lda);
#pragma unroll
    for (int r = 0; r < BREP; r++)
        stB[r] = TRANSB ? *(const float4*)(Bptr + (long long)r * 64 * ldb)
                        : *(const float4*)(Bptr + (long long)r * bkstep * ldb);
#pragma unroll
    for (int r = 0; r < AREP; r++)
        *(float4*)&As[0][arow + r * 64][ac4] = f2tf4(stA[r]);
#pragma unroll
    for (int r = 0; r < BREP; r++) {
        float4 bv = f2tf4(stB[r]);
        if (TRANSB) {
            Bs[0][ac4 + 0][arow + r * 64] = bv.x; Bs[0][ac4 + 1][arow + r * 64] = bv.y;
            Bs[0][ac4 + 2][arow + r * 64] = bv.z; Bs[0][ac4 + 3][arow + r * 64] = bv.w;
        } else {
            *(float4*)&Bs[0][bk0 + r * bkstep][bn4] = bv;
        }
    }
    __syncthreads();

    for (int t = 0; t < nt; t++) {
        const int cur = t & 1, nb = cur ^ 1;
        if (t + 1 < nt) {
            const long long ko = (long long)(t + 1) * BK;
#pragma unroll
            for (int r = 0; r < AREP; r++)
                stA[r] = *(const float4*)(Aptr + (long long)r * 64 * lda + ko);
#pragma unroll
            for (int r = 0; r < BREP; r++)
                stB[r] = TRANSB ? *(const float4*)(Bptr + (long long)r * 64 * ldb + ko)
                                : *(const float4*)(Bptr + ((long long)r * bkstep + ko) * ldb);
        }
#pragma unroll
        for (int ks = 0; ks < 2; ks++) {
            const int kb = ks * 8;
            uint32_t af[FM][4], bf[FN][2];
#pragma unroll
            for (int mi = 0; mi < FM; mi++) {
                const int row = wm + mi * 16 + g;
                af[mi][0] = __float_as_uint(As[cur][row    ][kb + tig]);
                af[mi][1] = __float_as_uint(As[cur][row + 8][kb + tig]);
                af[mi][2] = __float_as_uint(As[cur][row    ][kb + tig + 4]);
                af[mi][3] = __float_as_uint(As[cur][row + 8][kb + tig + 4]);
            }
#pragma unroll
            for (int ni = 0; ni < FN; ni++) {
                const int col = wn + ni * 8 + g;
                bf[ni][0] = __float_as_uint(Bs[cur][kb + tig    ][col]);
                bf[ni][1] = __float_as_uint(Bs[cur][kb + tig + 4][col]);
            }
#pragma unroll
            for (int mi = 0; mi < FM; mi++)
#pragma unroll
                for (int ni = 0; ni < FN; ni++) mma8(acc[mi][ni], af[mi], bf[ni]);
        }
        if (t + 1 < nt) {
#pragma unroll
            for (int r = 0; r < AREP; r++)
                *(float4*)&As[nb][arow + r * 64][ac4] = f2tf4(stA[r]);
#pragma unroll
            for (int r = 0; r < BREP; r++) {
                float4 bv = f2tf4(stB[r]);
                if (TRANSB) {
                    Bs[nb][ac4 + 0][arow + r * 64] = bv.x; Bs[nb][ac4 + 1][arow + r * 64] = bv.y;
                    Bs[nb][ac4 + 2][arow + r * 64] = bv.z; Bs[nb][ac4 + 3][arow + r * 64] = bv.w;
                } else {
                    *(float4*)&Bs[nb][bk0 + r * bkstep][bn4] = bv;
                }
            }
        }
        __syncthreads();
    }

#pragma unroll
    for (int mi = 0; mi < FM; mi++) {
        const int r0 = i0 + wm + mi * 16 + g;
        const int r1 = r0 + 8;
#pragma unroll
        for (int ni = 0; ni < FN; ni++) {
            const int c0 = j0 + wn + ni * 8 + 2 * tig;
            const float* d = acc[mi][ni];
            if (EPI == 0) {
                float2 v0 = make_float2(alpha * d[0], alpha * d[1]);
                float2 v1 = make_float2(alpha * d[2], alpha * d[3]);
                if (beta != 0.f) {
                    float2 e0 = *(const float2*)&A[(long long)r0 * lda + c0];
                    float2 e1 = *(const float2*)&A[(long long)r1 * lda + c0];
                    v0.x += beta * e0.x; v0.y += beta * e0.y;
                    v1.x += beta * e1.x; v1.y += beta * e1.y;
                }
                *(float2*)&C[(long long)r0 * ldc + c0] = v0;
                *(float2*)&C[(long long)r1 * ldc + c0] = v1;
            } else if (EPI == 1) {
                const int sec = c0 >> 9, rem = c0 & 511;
                const int h = rem >> 6, dd = rem & 63;
#pragma unroll
                for (int half = 0; half < 2; half++) {
                    const int r = half ? r1 : r0;
                    const int bb_ = r >> 12, nn_ = r & 4095;
                    const long long di = (((long long)(bb_ * H_ + h)) * N_ + nn_) * DH_ + dd;
                    float2 v = half ? make_float2(d[2], d[3]) : make_float2(d[0], d[1]);
                    if (sec == 0) { v.x *= 0.125f; v.y *= 0.125f; *(float2*)&O1[di] = v; }
                    else if (sec == 1) *(float2*)&O2[di] = v;
                    else               *(float2*)&O3[di] = v;
                }
            } else { // EPI == 2
                const long long d0i = (long long)r0 * DIM_ + c0;
                const long long d1i = (long long)r1 * DIM_ + c0;
                float2 e0 = *(const float2*)&E1[d0i];
                float2 e1 = *(const float2*)&E1[d1i];
                float2 b2 = *(const float2*)&E2[c0];
                *(float2*)&C[d0i] = make_float2(d[0] + e0.x + b2.x, d[1] + e0.y + b2.y);
                *(float2*)&C[d1i] = make_float2(d[2] + e1.x + b2.x, d[3] + e1.y + b2.y);
            }
        }
    }
}

// ------------------------- flash attention: O = softmax(Q@K^T) @ V -------------------
// Q: [bh, R, 64] (R = gridDim.x*64), K,V: [bh, C, 64], O: [bh, R, 64].
// 128 threads = 4 warps; each warp owns 16 rows; BC = 128 per chunk.
// Dynamic smem: Qs[64][68] | KP union(Ks[128][68], Ps[64][140]) | Vs[128][68].
#define FL_QS   0
#define FL_KP   (64 * 68)
#define FL_VS   (64 * 68 + 8960)
#define FL_SMEM ((64 * 68 + 8960 + 128 * 68) * 4)

__global__ __launch_bounds__(128) void flash_kernel(
    const float* __restrict__ Q, const float* __restrict__ K,
    const float* __restrict__ V, float* __restrict__ O, int C)
{
    extern __shared__ float sm[];
    float* Qs = sm + FL_QS;
    float* KP = sm + FL_KP;
    float* Vs = sm + FL_VS;

    const int bh = blockIdx.y;
    const long long qoff = ((long long)bh * gridDim.x + blockIdx.x) * 64 * 64;
    Q += qoff;  O += qoff;
    K += (long long)bh * C * 64;
    V += (long long)bh * C * 64;

    const int tid = threadIdx.x;
    const int lane = tid & 31, g = lane >> 2, tig = lane & 3;
    const int w = tid >> 5;
    const int r0l = w * 16 + g, r1l = r0l + 8;

    // load Q block (64x64)
#pragma unroll
    for (int i = 0; i < 8; i++) {
        int idx = tid + i * 128;
        int row = idx >> 4, c4 = (idx & 15) << 2;
        *(float4*)&Qs[row * 68 + c4] = f2tf4(*(const float4*)&Q[row * 64 + c4]);
    }

    float o[8][4] = {};
    float m0 = -1e30f, m1 = -1e30f, l0 = 0.f, l1 = 0.f;

    for (int c0 = 0; c0 < C; c0 += 128) {
        __syncthreads();
        // load K,V chunk (128x64 each)
#pragma unroll
        for (int i = 0; i < 16; i++) {
            int idx = tid + i * 128;
            int row = idx >> 4, c4 = (idx & 15) << 2;
            *(float4*)&KP[row * 68 + c4] = f2tf4(*(const float4*)&K[(long long)(c0 + row) * 64 + c4]);
            *(float4*)&Vs[row * 68 + c4] = f2tf4(*(const float4*)&V[(long long)(c0 + row) * 64 + c4]);
        }
        __syncthreads();

        // S = Q @ K^T  (16 rows x 128 cols per warp)
        float s[16][4] = {};
#pragma unroll
        for (int kb = 0; kb < 64; kb += 8) {
            uint32_t af[4];
            af[0] = __float_as_uint(Qs[r0l * 68 + kb + tig]);
            af[1] = __float_as_uint(Qs[r1l * 68 + kb + tig]);
            af[2] = __float_as_uint(Qs[r0l * 68 + kb + tig + 4]);
            af[3] = __float_as_uint(Qs[r1l * 68 + kb + tig + 4]);
#pragma unroll
            for (int ni = 0; ni < 16; ni++) {
                uint32_t bf[2];
                bf[0] = __float_as_uint(KP[(ni * 8 + g) * 68 + kb + tig]);
                bf[1] = __float_as_uint(KP[(ni * 8 + g) * 68 + kb + tig + 4]);
                mma8(s[ni], af, bf);
            }
        }

        // online softmax
        float cm0 = -1e30f, cm1 = -1e30f;
#pragma unroll
        for (int ni = 0; ni < 16; ni++) {
            cm0 = fmaxf(cm0, fmaxf(s[ni][0], s[ni][1]));
            cm1 = fmaxf(cm1, fmaxf(s[ni][2], s[ni][3]));
        }
        cm0 = fmaxf(cm0, __shfl_xor_sync(0xffffffffu, cm0, 1));
        cm0 = fmaxf(cm0, __shfl_xor_sync(0xffffffffu, cm0, 2));
        cm1 = fmaxf(cm1, __shfl_xor_sync(0xffffffffu, cm1, 1));
        cm1 = fmaxf(cm1, __shfl_xor_sync(0xffffffffu, cm1, 2));
        float M0 = fmaxf(m0, cm0), M1 = fmaxf(m1, cm1);
        float corr0 = __expf(m0 - M0), corr1 = __expf(m1 - M1);
        float sum0 = 0.f, sum1 = 0.f;
#pragma unroll
        for (int ni = 0; ni < 16; ni++) {
            s[ni][0] = __expf(s[ni][0] - M0);
            s[ni][1] = __expf(s[ni][1] - M0);
            s[ni][2] = __expf(s[ni][2] - M1);
            s[ni][3] = __expf(s[ni][3] - M1);
            sum0 += s[ni][0] + s[ni][1];
            sum1 += s[ni][2] + s[ni][3];
        }
        sum0 += __shfl_xor_sync(0xffffffffu, sum0, 1);
        sum0 += __shfl_xor_sync(0xffffffffu, sum0, 2);
        sum1 += __shfl_xor_sync(0xffffffffu, sum1, 1);
        sum1 += __shfl_xor_sync(0xffffffffu, sum1, 2);
        l0 = l0 * corr0 + sum0;
        l1 = l1 * corr1 + sum1;
        m0 = M0; m1 = M1;
#pragma unroll
        for (int ni = 0; ni < 8; ni++) {
            o[ni][0] *= corr0; o[ni][1] *= corr0;
            o[ni][2] *= corr1; o[ni][3] *= corr1;
        }

        __syncthreads();      // all warps done reading K tile (Ps aliases it)
        // write P (tf32) to Ps[64][140]
#pragma unroll
        for (int ni = 0; ni < 16; ni++) {
            int col = ni * 8 + 2 * tig;
            *(float2*)&KP[r0l * 140 + col] = make_float2(f2tf(s[ni][0]), f2tf(s[ni][1]));
            *(float2*)&KP[r1l * 140 + col] = make_float2(f2tf(s[ni][2]), f2tf(s[ni][3]));
        }
        __syncthreads();

        // O += P @ V   (K = 128)
#pragma unroll
        for (int kb = 0; kb < 128; kb += 8) {
            uint32_t af[4];
            af[0] = __float_as_uint(KP[r0l * 140 + kb + tig]);
            af[1] = __float_as_uint(KP[r1l * 140 + kb + tig]);
            af[2] = __float_as_uint(KP[r0l * 140 + kb + tig + 4]);
            af[3] = __float_as_uint(KP[r1l * 140 + kb + tig + 4]);
#pragma unroll
            for (int ni = 0; ni < 8; ni++) {
                uint32_t bf[2];
                bf[0] = __float_as_uint(Vs[(kb + tig) * 68 + ni * 8 + g]);
                bf[1] = __float_as_uint(Vs[(kb + tig + 4) * 68 + ni * 8 + g]);
                mma8(o[ni], af, bf);
            }
        }
    }

    const float inv0 = 1.f / l0, inv1 = 1.f / l1;
#pragma unroll
    for (int ni = 0; ni < 8; ni++) {
        int col = ni * 8 + 2 * tig;
        *(float2*)&O[r0l * 64 + col] = make_float2(o[ni][0] * inv0, o[ni][1] * inv0);
        *(float2*)&O[r1l * 64 + col] = make_float2(o[ni][2] * inv1, o[ni][3] * inv1);
    }
}

// ------------------------- landmarks (mean over 16 tokens) -------------------------
__global__ void landmark_kernel(const float* __restrict__ q, const float* __restrict__ k,
                                float* __restrict__ ql, float* __restrict__ kl) {
    int idx = blockIdx.x * 256 + threadIdx.x;      // BH_*M_*DH_ = 524288
    int d = idx & 63;
    int m = (idx >> 6) & 255;
    int bh = idx >> 14;
    long long base = ((long long)bh * N_ + m * 16) * DH_ + d;
    float sq = 0.f, sk = 0.f;
#pragma unroll
    for (int j = 0; j < 16; j++) {
        sq += q[base + (long long)j * DH_];
        sk += k[base + (long long)j * DH_];
    }
    ql[idx] = sq * (1.f / 16.f);
    kl[idx] = sk * (1.f / 16.f);
}

// ------------------------- softmax over last dim (a2 only) -------------------------
__global__ void softmax_kernel(float* __restrict__ p) {
    __shared__ float sh[8];
    float* r = p + (long long)blockIdx.x * 256;
    float v = r[threadIdx.x];
    float mx = blockMax(v, sh, 8);
    float e = expf(v - mx);
    float s = blockSum(e, sh, 8);
    r[threadIdx.x] = e / s;
}

// ------------------------- pinv init helpers -------------------------
// a2 rows are softmax outputs: row sums == 1, so max over dim(-1) sums == 1.
// Only the max over column sums (dim -2) is needed.
__global__ void init_max_kernel() {
    if (threadIdx.x == 0) g_max = 0u;
}
__global__ void colsum_max_kernel(const float* __restrict__ a2) {
    __shared__ float sh[8];
    int bh = blockIdx.x >> 8, j = blockIdx.x & 255;
    float v = fabsf(a2[(long long)bh * M_ * M_ + (long long)threadIdx.x * M_ + j]);
    float s = blockSum(v, sh, 8);
    if (threadIdx.x == 0) atomicMax(&g_max, __float_as_uint(s));
}
__global__ void zinit_kernel(const float* __restrict__ a2, float* __restrict__ z) {
    int idx = blockIdx.x * 256 + threadIdx.x;       // BH_*M_*M_
    int j = idx & 255, i = (idx >> 8) & 255, bh = idx >> 16;
    float scale = 1.f / __uint_as_float(g_max);
    z[idx] = a2[(long long)bh * M_ * M_ + (long long)j * M_ + i] * scale;
}

// ------------------------- tiled depthwise conv + merge heads -------------------------
#define VSTR 68
__global__ __launch_bounds__(256) void conv_merge_kernel(
    const float* __restrict__ v, const float* __restrict__ oat,
    const float* __restrict__ wconv, float* __restrict__ outc)
{
    __shared__ float vt[160 * VSTR];
    __shared__ float wc[KC_];
    const int bh = blockIdx.y, h = bh & 7, b = bh >> 3;
    const int n0 = blockIdx.x * 128;
    const int tid = threadIdx.x;
    if (tid < KC_) wc[tid] = wconv[h * KC_ + tid];
    const float* vb = v + (long long)bh * N_ * DH_;
#pragma unroll
    for (int i = 0; i < 10; i++) {
        int idx = tid + i * 256;                    // 2560 float4 slots = 160 rows x 16
        int row = idx >> 4, c4 = (idx & 15) << 2;
        int gn = n0 - 16 + row;
        float4 val = make_float4(0.f, 0.f, 0.f, 0.f);
        if (gn >= 0 && gn < N_) val = *(const float4*)&vb[(long long)gn * DH_ + c4];
        *(float4*)&vt[row * VSTR + c4] = val;
    }
    __syncthreads();
    const float* ob = oat + (long long)bh * N_ * DH_;
    float* outb = outc + ((long long)b * N_ + n0) * DIM_ + h * DH_;
#pragma unroll 4
    for (int i = 0; i < 32; i++) {
        int idx = tid + i * 256;
        int nl = idx >> 6, d = idx & 63;
        float r = 0.f;
#pragma unroll
        for (int kk = 0; kk < KC_; kk++) r = fmaf(vt[(nl + kk) * VSTR + d], wc[kk], r);
        outb[(long long)nl * DIM_ + d] = ob[(long long)(n0 + nl) * DH_ + d] + r;
    }
}

// ------------------------- host launcher -------------------------
extern "C" void kernel_launch(void* const* d_in, const int* in_sizes, int n_in,
                              void* d_out, int out_size) {
    const float* x      = (const float*)d_in[0];
    const float* ln_w   = (const float*)d_in[1];
    const float* ln_b   = (const float*)d_in[2];
    const float* w_qkv  = (const float*)d_in[3];
    const float* w_out  = (const float*)d_in[4];
    const float* b_out  = (const float*)d_in[5];
    const float* w_conv = (const float*)d_in[6];
    float* out = (float*)d_out;

    float *p_xn, *p_q, *p_k, *p_v, *p_ql, *p_kl, *p_a2;
    float *p_zA, *p_zB, *p_xz, *p_t1, *p_t2, *p_a3v, *p_zv, *p_oat, *p_outc;
    cudaGetSymbolAddress((void**)&p_xn,  g_xn);
    cudaGetSymbolAddress((void**)&p_q,   g_q);
    cudaGetSymbolAddress((void**)&p_k,   g_k);
    cudaGetSymbolAddress((void**)&p_v,   g_v);
    cudaGetSymbolAddress((void**)&p_ql,  g_ql);
    cudaGetSymbolAddress((void**)&p_kl,  g_kl);
    cudaGetSymbolAddress((void**)&p_a2,  g_a2);
    cudaGetSymbolAddress((void**)&p_zA,  g_zA);
    cudaGetSymbolAddress((void**)&p_zB,  g_zB);
    cudaGetSymbolAddress((void**)&p_xz,  g_xz);
    cudaGetSymbolAddress((void**)&p_t1,  g_t1);
    cudaGetSymbolAddress((void**)&p_t2,  g_t2);
    cudaGetSymbolAddress((void**)&p_a3v, g_a3v);
    cudaGetSymbolAddress((void**)&p_zv,  g_zv);
    cudaGetSymbolAddress((void**)&p_oat, g_oat);
    cudaGetSymbolAddress((void**)&p_outc,g_outc);

    static cudaStream_t s2 = nullptr;
    static cudaEvent_t evFork = nullptr, evJoin = nullptr;
    static int init_done = 0;
    if (!init_done) {
        cudaFuncSetAttribute(flash_kernel, cudaFuncAttributeMaxDynamicSharedMemorySize, FL_SMEM);
        cudaStreamCreateWithFlags(&s2, cudaStreamNonBlocking);
        cudaEventCreateWithFlags(&evFork, cudaEventDisableTiming);
        cudaEventCreateWithFlags(&evJoin, cudaEventDisableTiming);
        init_done = 1;
    }

    const long long sL  = (long long)M_ * DH_;      // 16384
    const long long sM2 = (long long)M_ * M_;       // 65536

    // 1. LayerNorm
    ln_kernel<<<B_ * N_, 128>>>(x, ln_w, ln_b, p_xn);

    // 2. QKV GEMM [16384,512] @ [512,1536] -> scatter into q/k/v [bh,n,dh]
    mma_gemm<128, 128, 2, 1, false><<<dim3(12, 128, 1), 256>>>(
        p_xn, w_qkv, nullptr, 512, 512, 1536, 0, 0, 0, 0, 1.f, 0.f,
        nullptr, nullptr, p_q, p_k, p_v);

    // 3. Landmarks (mean over 16 tokens)
    landmark_kernel<<<(BH_ * M_ * DH_) / 256, 256>>>(p_q, p_k, p_ql, p_kl);

    // ---- fork: flash3 runs concurrently with the sim2/softmax/pinv chain ----
    cudaEventRecord(evFork, 0);
    cudaStreamWaitEvent(s2, evFork, 0);

    // s2: flash3: a3v = softmax(ql @ k^T) @ v   [bh,256,64]
    flash_kernel<<<dim3(M_ / 64, BH_), 128, FL_SMEM, s2>>>(p_ql, p_k, p_v, p_a3v, N_);
    cudaEventRecord(evJoin, s2);

    // main: sim2 = ql @ kl^T [256,256] + softmax
    mma_gemm<128, 128, 2, 0, true><<<dim3(2, 2, BH_), 256>>>(
        p_ql, p_kl, p_a2, 64, 64, 64, 256, sL, sL, sM2, 1.f, 0.f,
        nullptr, nullptr, nullptr, nullptr, nullptr);
    softmax_kernel<<<BH_ * M_, 256>>>(p_a2);

    // pinv init (row-sum max == 1 since a2 rows are softmaxed)
    init_max_kernel<<<1, 32>>>();
    colsum_max_kernel<<<BH_ * M_, 256>>>(p_a2);
    zinit_kernel<<<(BH_ * M_ * M_) / 256, 256>>>(p_a2, p_zA);

    // Newton-Schulz iterations (batched 256^3 GEMMs, 32 matrices)
    float* cur = p_zA;
    float* nxt = p_zB;
    for (int it = 0; it < ITERS_; it++) {
        mma_gemm<128, 128, 2, 0, false><<<dim3(2, 2, BH_), 256>>>(
            p_a2, cur, p_xz, 256, 256, 256, 256, sM2, sM2, sM2, 1.f, 0.f,
            nullptr, nullptr, nullptr, nullptr, nullptr);
        mma_gemm<128, 128, 2, 0, false><<<dim3(2, 2, BH_), 256>>>(
            p_xz, p_xz, p_t1, 256, 256, 256, 256, sM2, sM2, sM2, -1.f, 7.f,
            nullptr, nullptr, nullptr, nullptr, nullptr);
        mma_gemm<128, 128, 2, 0, false><<<dim3(2, 2, BH_), 256>>>(
            p_xz, p_t1, p_t2, 256, 256, 256, 256, sM2, sM2, sM2, -1.f, 15.f,
            nullptr, nullptr, nullptr, nullptr, nullptr);
        mma_gemm<128, 128, 2, 0, false><<<dim3(2, 2, BH_), 256>>>(
            cur, p_t2, nxt, 256, 256, 256, 256, sM2, sM2, sM2, -0.25f, 3.25f,
            nullptr, nullptr, nullptr, nullptr, nullptr);
        float* tmp = cur; cur = nxt; nxt = tmp;
    }

    // ---- join: zv needs both pinv result (main) and a3v (s2) ----
    cudaStreamWaitEvent(0, evJoin, 0);

    // zv = a2inv @ a3v  [256,64]
    mma_gemm<128, 64, 4, 0, false><<<dim3(1, 2, BH_), 256>>>(
        cur, p_a3v, p_zv, 256, 256, 64, 64, sM2, sL, sL, 1.f, 0.f,
        nullptr, nullptr, nullptr, nullptr, nullptr);

    // flash1: oat = softmax(q @ kl^T) @ zv   [bh,4096,64]
    flash_kernel<<<dim3(N_ / 64, BH_), 128, FL_SMEM>>>(p_q, p_kl, p_zv, p_oat, M_);

    // depthwise conv residual + head merge -> [b*n, 512]
    conv_merge_kernel<<<dim3(N_ / 128, BH_), 256>>>(p_v, p_oat, w_conv, p_outc);

    // final: out = x + outc @ w_out + b_out
    mma_gemm<128, 128, 2, 2, false><<<dim3(4, 128, 1), 256>>>(
        p_outc, w_out, out, 512, 512, 512, 512, 0, 0, 0, 1.f, 0.f,
        x, b_out, nullptr, nullptr, nullptr);
}

// round 12
// speedup vs baseline: 1.1300x; 1.0051x over previous
#include <cuda_runtime.h>
#include <cstdint>

// Problem constants
#define B_      4
#define N_      4096
#define DIM_    512
#define H_      8
#define DH_     64
#define M_      256
#define BH_     32          // B_*H_
#define ITERS_  6
#define KC_     33
#define YOFF_   (32LL * 65536LL)   // y half offset inside zy buffers

// ------------------------- scratch (device globals) -------------------------
__device__ float g_xn  [B_ * N_ * DIM_];
__device__ float g_q   [BH_ * N_ * DH_];
__device__ float g_k   [BH_ * N_ * DH_];
__device__ float g_v   [BH_ * N_ * DH_];
__device__ float g_ql  [BH_ * M_ * DH_];
__device__ float g_kl  [BH_ * M_ * DH_];
__device__ float g_a2  [BH_ * M_ * M_];
__device__ float g_zyA [2 * BH_ * M_ * M_];   // [z(32) | y(32)]
__device__ float g_zyB [2 * BH_ * M_ * M_];
__device__ float g_p1  [BH_ * M_ * M_];
__device__ float g_t2  [BH_ * M_ * M_];
__device__ float g_a3v [BH_ * M_ * DH_];
__device__ float g_zv  [BH_ * M_ * DH_];
__device__ float g_outc[B_ * N_ * DIM_];
__device__ unsigned g_max;

// ------------------------- reductions -------------------------
__device__ __forceinline__ float warpSum(float v) {
#pragma unroll
    for (int o = 16; o > 0; o >>= 1) v += __shfl_xor_sync(0xffffffffu, v, o);
    return v;
}
__device__ __forceinline__ float warpMax(float v) {
#pragma unroll
    for (int o = 16; o > 0; o >>= 1) v = fmaxf(v, __shfl_xor_sync(0xffffffffu, v, o));
    return v;
}
__device__ __forceinline__ float blockSum(float v, float* sh, int nw) {
    int l = threadIdx.x & 31, w = threadIdx.x >> 5;
    v = warpSum(v);
    if (l == 0) sh[w] = v;
    __syncthreads();
    if (w == 0) {
        float x = (l < nw) ? sh[l] : 0.f;
        x = warpSum(x);
        if (l == 0) sh[0] = x;
    }
    __syncthreads();
    float r = sh[0];
    __syncthreads();
    return r;
}
__device__ __forceinline__ float blockMax(float v, float* sh, int nw) {
    int l = threadIdx.x & 31, w = threadIdx.x >> 5;
    v = warpMax(v);
    if (l == 0) sh[w] = v;
    __syncthreads();
    if (w == 0) {
        float x = (l < nw) ? sh[l] : -3.4e38f;
        x = warpMax(x);
        if (l == 0) sh[0] = x;
    }
    __syncthreads();
    float r = sh[0];
    __syncthreads();
    return r;
}

// ------------------------- tf32 helpers -------------------------
__device__ __forceinline__ float f2tf(float x) {
    uint32_t r;
    asm("cvt.rna.tf32.f32 %0, %1;" : "=r"(r) : "f"(x));
    return __uint_as_float(r);
}
__device__ __forceinline__ float4 f2tf4(float4 v) {
    return make_float4(f2tf(v.x), f2tf(v.y), f2tf(v.z), f2tf(v.w));
}
__device__ __forceinline__ void mma8(float* d, const uint32_t* a, const uint32_t* b) {
    asm volatile(
        "mma.sync.aligned.m16n8k8.row.col.f32.tf32.tf32.f32 "
        "{%0,%1,%2,%3}, {%4,%5,%6,%7}, {%8,%9}, {%0,%1,%2,%3};\n"
        : "+f"(d[0]), "+f"(d[1]), "+f"(d[2]), "+f"(d[3])
        : "r"(a[0]), "r"(a[1]), "r"(a[2]), "r"(a[3]), "r"(b[0]), "r"(b[1]));
}

// ------------------------- layernorm -------------------------
__global__ void ln_kernel(const float* __restrict__ x, const float* __restrict__ w,
                          const float* __restrict__ b, float* __restrict__ xn) {
    __shared__ float sh[8];
    long long row = blockIdx.x;
    const float4* p = (const float4*)(x + row * DIM_);
    float4 v = p[threadIdx.x];                       // 128 threads * 4
    float s  = v.x + v.y + v.z + v.w;
    float sq = v.x * v.x + v.y * v.y + v.z * v.z + v.w * v.w;
    s  = blockSum(s,  sh, 4);
    sq = blockSum(sq, sh, 4);
    float mean = s * (1.f / DIM_);
    float var  = sq * (1.f / DIM_) - mean * mean;
    float rstd = rsqrtf(var + 1e-5f);
    float4 wv = ((const float4*)w)[threadIdx.x];
    float4 bv = ((const float4*)b)[threadIdx.x];
    float4 o;
    o.x = (v.x - mean) * rstd * wv.x + bv.x;
    o.y = (v.y - mean) * rstd * wv.y + bv.y;
    o.z = (v.z - mean) * rstd * wv.z + bv.z;
    o.w = (v.w - mean) * rstd * wv.w + bv.w;
    ((float4*)(xn + row * DIM_))[threadIdx.x] = o;
}

// ------------------------- tf32 tensor-core GEMM -------------------------
// C = alpha*(A @ opB) + beta*A   (beta path used by square pinv GEMMs)
// EPI 0: standard.  EPI 1: qkv scatter into q/k/v.  EPI 2: += x + b_out.
// BMOD: B batch index = bz & 31 (for the batched [z,y] pinv step).
template<int BM, int BN, int WRS, int EPI, bool TRANSB, bool BMOD = false>
__global__ __launch_bounds__(256) void mma_gemm(
    const float* __restrict__ A, const float* __restrict__ B, float* __restrict__ C,
    int Kper, int lda, int ldb, int ldc,
    long long sA, long long sB, long long sC,
    float alpha, float beta,
    const float* __restrict__ E1, const float* __restrict__ E2,
    float* __restrict__ O1, float* __restrict__ O2, float* __restrict__ O3)
{
    constexpr int BK  = 16;
    constexpr int WCS = 8 / WRS;
    constexpr int WM  = BM / WRS;
    constexpr int WN  = BN / WCS;
    constexpr int FM  = WM / 16;
    constexpr int FN  = WN / 8;
    constexpr int SKA = BK + 4;
    constexpr int SNB = BN + 8;
    constexpr int AREP = BM / 64;
    constexpr int BREP = BN / 64;

    __shared__ float As[2][BM][SKA];   // [m][k]
    __shared__ float Bs[2][BK][SNB];   // [k][n]

    const int bz = blockIdx.z;
    const int bzb = BMOD ? (bz & 31) : bz;
    A += bz * sA;
    B += (long long)bzb * sB;
    if (C) C += bz * sC;

    const int i0 = blockIdx.y * BM, j0 = blockIdx.x * BN;
    const int tid  = threadIdx.x;
    const int lane = tid & 31, g = lane >> 2, tig = lane & 3;
    const int wid  = tid >> 5;
    const int wm   = (wid / WCS) * WM;
    const int wn   = (wid % WCS) * WN;

    const int arow = tid >> 2, ac4 = (tid & 3) << 2;
    const int bnn4 = BN / 4;
    const int bk0  = tid / bnn4, bn4 = (tid % bnn4) << 2;
    const int bkstep = 1024 / BN;

    const float* Aptr = &A[(long long)(i0 + arow) * lda + ac4];
    const float* Bptr = TRANSB ? &B[(long long)(j0 + arow) * ldb + ac4]
                               : &B[(long long)bk0 * ldb + j0 + bn4];

    float acc[FM][FN][4] = {};
    const int nt = Kper / BK;

    float4 stA[AREP], stB[BREP];

#pragma unroll
    for (int r = 0; r < AREP; r++) stA[r] = *(const float4*)(Aptr + (long long)r * 64 * lda);
#pragma unroll
    for (int r = 0; r < BREP; r++)
        stB[r] = TRANSB ? *(const float4*)(Bptr + (long long)r * 64 * ldb)
                        : *(const float4*)(Bptr + (long long)r * bkstep * ldb);
#pragma unroll
    for (int r = 0; r < AREP; r++)
        *(float4*)&As[0][arow + r * 64][ac4] = f2tf4(stA[r]);
#pragma unroll
    for (int r = 0; r < BREP; r++) {
        float4 bv = f2tf4(stB[r]);
        if (TRANSB) {
            Bs[0][ac4 + 0][arow + r * 64] = bv.x; Bs[0][ac4 + 1][arow + r * 64] = bv.y;
            Bs[0][ac4 + 2][arow + r * 64] = bv.z; Bs[0][ac4 + 3][arow + r * 64] = bv.w;
        } else {
            *(float4*)&Bs[0][bk0 + r * bkstep][bn4] = bv;
        }
    }
    __syncthreads();

    for (int t = 0; t < nt; t++) {
        const int cur = t & 1, nb = cur ^ 1;
        if (t + 1 < nt) {
            const long long ko = (long long)(t + 1) * BK;
#pragma unroll
            for (int r = 0; r < AREP; r++)
                stA[r] = *(const float4*)(Aptr + (long long)r * 64 * lda + ko);
#pragma unroll
            for (int r = 0; r < BREP; r++)
                stB[r] = TRANSB ? *(const float4*)(Bptr + (long long)r * 64 * ldb + ko)
                                : *(const float4*)(Bptr + ((long long)r * bkstep + ko) * ldb);
        }
#pragma unroll
        for (int ks = 0; ks < 2; ks++) {
            const int kb = ks * 8;
            uint32_t af[FM][4], bf[FN][2];
#pragma unroll
            for (int mi = 0; mi < FM; mi++) {
                const int row = wm + mi * 16 + g;
                af[mi][0] = __float_as_uint(As[cur][row    ][kb + tig]);
                af[mi][1] = __float_as_uint(As[cur][row + 8][kb + tig]);
                af[mi][2] = __float_as_uint(As[cur][row    ][kb + tig + 4]);
                af[mi][3] = __float_as_uint(As[cur][row + 8][kb + tig + 4]);
            }
#pragma unroll
            for (int ni = 0; ni < FN; ni++) {
                const int col = wn + ni * 8 + g;
                bf[ni][0] = __float_as_uint(Bs[cur][kb + tig    ][col]);
                bf[ni][1] = __float_as_uint(Bs[cur][kb + tig + 4][col]);
            }
#pragma unroll
            for (int mi = 0; mi < FM; mi++)
#pragma unroll
                for (int ni = 0; ni < FN; ni++) mma8(acc[mi][ni], af[mi], bf[ni]);
        }
        if (t + 1 < nt) {
#pragma unroll
            for (int r = 0; r < AREP; r++)
                *(float4*)&As[nb][arow + r * 64][ac4] = f2tf4(stA[r]);
#pragma unroll
            for (int r = 0; r < BREP; r++) {
                float4 bv = f2tf4(stB[r]);
                if (TRANSB) {
                    Bs[nb][ac4 + 0][arow + r * 64] = bv.x; Bs[nb][ac4 + 1][arow + r * 64] = bv.y;
                    Bs[nb][ac4 + 2][arow + r * 64] = bv.z; Bs[nb][ac4 + 3][arow + r * 64] = bv.w;
                } else {
                    *(float4*)&Bs[nb][bk0 + r * bkstep][bn4] = bv;
                }
            }
        }
        __syncthreads();
    }

#pragma unroll
    for (int mi = 0; mi < FM; mi++) {
        const int r0 = i0 + wm + mi * 16 + g;
        const int r1 = r0 + 8;
#pragma unroll
        for (int ni = 0; ni < FN; ni++) {
            const int c0 = j0 + wn + ni * 8 + 2 * tig;
            const float* d = acc[mi][ni];
            if (EPI == 0) {
                float2 v0 = make_float2(alpha * d[0], alpha * d[1]);
                float2 v1 = make_float2(alpha * d[2], alpha * d[3]);
                if (beta != 0.f) {
                    float2 e0 = *(const float2*)&A[(long long)r0 * lda + c0];
                    float2 e1 = *(const float2*)&A[(long long)r1 * lda + c0];
                    v0.x += beta * e0.x; v0.y += beta * e0.y;
                    v1.x += beta * e1.x; v1.y += beta * e1.y;
                }
                *(float2*)&C[(long long)r0 * ldc + c0] = v0;
                *(float2*)&C[(long long)r1 * ldc + c0] = v1;
            } else if (EPI == 1) {
                const int sec = c0 >> 9, rem = c0 & 511;
                const int h = rem >> 6, dd = rem & 63;
#pragma unroll
                for (int half = 0; half < 2; half++) {
                    const int r = half ? r1 : r0;
                    const int bb_ = r >> 12, nn_ = r & 4095;
                    const long long di = (((long long)(bb_ * H_ + h)) * N_ + nn_) * DH_ + dd;
                    float2 v = half ? make_float2(d[2], d[3]) : make_float2(d[0], d[1]);
                    if (sec == 0) { v.x *= 0.125f; v.y *= 0.125f; *(float2*)&O1[di] = v; }
                    else if (sec == 1) *(float2*)&O2[di] = v;
                    else               *(float2*)&O3[di] = v;
                }
            } else { // EPI == 2
                const long long d0i = (long long)r0 * DIM_ + c0;
                const long long d1i = (long long)r1 * DIM_ + c0;
                float2 e0 = *(const float2*)&E1[d0i];
                float2 e1 = *(const float2*)&E1[d1i];
                float2 b2 = *(const float2*)&E2[c0];
                *(float2*)&C[d0i] = make_float2(d[0] + e0.x + b2.x, d[1] + e0.y + b2.y);
                *(float2*)&C[d1i] = make_float2(d[2] + e1.x + b2.x, d[3] + e1.y + b2.y);
            }
        }
    }
}

// ------------------------- flash attention: O = softmax(Q@K^T) @ V -------------------
// Q: [bh, R, 64] (R = gridDim.x*64), K,V: [bh, C, 64].
// scatter==0: O written [bh, R, 64].
// scatter==1: O[(b*N + n)*DIM + h*64 + d] += result (merged-head accumulate).
#define FL_QS   0
#define FL_KP   (64 * 68)
#define FL_VS   (64 * 68 + 8960)
#define FL_SMEM ((64 * 68 + 8960 + 128 * 68) * 4)

__global__ __launch_bounds__(128) void flash_kernel(
    const float* __restrict__ Q, const float* __restrict__ K,
    const float* __restrict__ V, float* __restrict__ O, int C, int scatter)
{
    extern __shared__ float sm[];
    float* Qs = sm + FL_QS;
    float* KP = sm + FL_KP;
    float* Vs = sm + FL_VS;

    const int bh = blockIdx.y;
    const long long qoff = ((long long)bh * gridDim.x + blockIdx.x) * 64 * 64;
    Q += qoff;
    K += (long long)bh * C * 64;
    V += (long long)bh * C * 64;

    const int tid = threadIdx.x;
    const int lane = tid & 31, g = lane >> 2, tig = lane & 3;
    const int w = tid >> 5;
    const int r0l = w * 16 + g, r1l = r0l + 8;

    // load Q block (64x64)
#pragma unroll
    for (int i = 0; i < 8; i++) {
        int idx = tid + i * 128;
        int row = idx >> 4, c4 = (idx & 15) << 2;
        *(float4*)&Qs[row * 68 + c4] = f2tf4(*(const float4*)&Q[row * 64 + c4]);
    }

    float o[8][4] = {};
    float m0 = -1e30f, m1 = -1e30f, l0 = 0.f, l1 = 0.f;

    for (int c0 = 0; c0 < C; c0 += 128) {
        __syncthreads();
        // load K,V chunk (128x64 each)
#pragma unroll
        for (int i = 0; i < 16; i++) {
            int idx = tid + i * 128;
            int row = idx >> 4, c4 = (idx & 15) << 2;
            *(float4*)&KP[row * 68 + c4] = f2tf4(*(const float4*)&K[(long long)(c0 + row) * 64 + c4]);
            *(float4*)&Vs[row * 68 + c4] = f2tf4(*(const float4*)&V[(long long)(c0 + row) * 64 + c4]);
        }
        __syncthreads();

        // S = Q @ K^T  (16 rows x 128 cols per warp)
        float s[16][4] = {};
#pragma unroll
        for (int kb = 0; kb < 64; kb += 8) {
            uint32_t af[4];
            af[0] = __float_as_uint(Qs[r0l * 68 + kb + tig]);
            af[1] = __float_as_uint(Qs[r1l * 68 + kb + tig]);
            af[2] = __float_as_uint(Qs[r0l * 68 + kb + tig + 4]);
            af[3] = __float_as_uint(Qs[r1l * 68 + kb + tig + 4]);
#pragma unroll
            for (int ni = 0; ni < 16; ni++) {
                uint32_t bf[2];
                bf[0] = __float_as_uint(KP[(ni * 8 + g) * 68 + kb + tig]);
                bf[1] = __float_as_uint(KP[(ni * 8 + g) * 68 + kb + tig + 4]);
                mma8(s[ni], af, bf);
            }
        }

        // online softmax
        float cm0 = -1e30f, cm1 = -1e30f;
#pragma unroll
        for (int ni = 0; ni < 16; ni++) {
            cm0 = fmaxf(cm0, fmaxf(s[ni][0], s[ni][1]));
            cm1 = fmaxf(cm1, fmaxf(s[ni][2], s[ni][3]));
        }
        cm0 = fmaxf(cm0, __shfl_xor_sync(0xffffffffu, cm0, 1));
        cm0 = fmaxf(cm0, __shfl_xor_sync(0xffffffffu, cm0, 2));
        cm1 = fmaxf(cm1, __shfl_xor_sync(0xffffffffu, cm1, 1));
        cm1 = fmaxf(cm1, __shfl_xor_sync(0xffffffffu, cm1, 2));
        float M0 = fmaxf(m0, cm0), M1 = fmaxf(m1, cm1);
        float corr0 = __expf(m0 - M0), corr1 = __expf(m1 - M1);
        float sum0 = 0.f, sum1 = 0.f;
#pragma unroll
        for (int ni = 0; ni < 16; ni++) {
            s[ni][0] = __expf(s[ni][0] - M0);
            s[ni][1] = __expf(s[ni][1] - M0);
            s[ni][2] = __expf(s[ni][2] - M1);
            s[ni][3] = __expf(s[ni][3] - M1);
            sum0 += s[ni][0] + s[ni][1];
            sum1 += s[ni][2] + s[ni][3];
        }
        sum0 += __shfl_xor_sync(0xffffffffu, sum0, 1);
        sum0 += __shfl_xor_sync(0xffffffffu, sum0, 2);
        sum1 += __shfl_xor_sync(0xffffffffu, sum1, 1);
        sum1 += __shfl_xor_sync(0xffffffffu, sum1, 2);
        l0 = l0 * corr0 + sum0;
        l1 = l1 * corr1 + sum1;
        m0 = M0; m1 = M1;
#pragma unroll
        for (int ni = 0; ni < 8; ni++) {
            o[ni][0] *= corr0; o[ni][1] *= corr0;
            o[ni][2] *= corr1; o[ni][3] *= corr1;
        }

        __syncthreads();      // all warps done reading K tile (Ps aliases it)
        // write P (tf32) to Ps[64][140]
#pragma unroll
        for (int ni = 0; ni < 16; ni++) {
            int col = ni * 8 + 2 * tig;
            *(float2*)&KP[r0l * 140 + col] = make_float2(f2tf(s[ni][0]), f2tf(s[ni][1]));
            *(float2*)&KP[r1l * 140 + col] = make_float2(f2tf(s[ni][2]), f2tf(s[ni][3]));
        }
        __syncthreads();

        // O += P @ V   (K = 128)
#pragma unroll
        for (int kb = 0; kb < 128; kb += 8) {
            uint32_t af[4];
            af[0] = __float_as_uint(KP[r0l * 140 + kb + tig]);
            af[1] = __float_as_uint(KP[r1l * 140 + kb + tig]);
            af[2] = __float_as_uint(KP[r0l * 140 + kb + tig + 4]);
            af[3] = __float_as_uint(KP[r1l * 140 + kb + tig + 4]);
#pragma unroll
            for (int ni = 0; ni < 8; ni++) {
                uint32_t bf[2];
                bf[0] = __float_as_uint(Vs[(kb + tig) * 68 + ni * 8 + g]);
                bf[1] = __float_as_uint(Vs[(kb + tig + 4) * 68 + ni * 8 + g]);
                mma8(o[ni], af, bf);
            }
        }
    }

    const float inv0 = 1.f / l0, inv1 = 1.f / l1;
    if (scatter == 0) {
        float* Op = O + qoff;
#pragma unroll
        for (int ni = 0; ni < 8; ni++) {
            int col = ni * 8 + 2 * tig;
            *(float2*)&Op[r0l * 64 + col] = make_float2(o[ni][0] * inv0, o[ni][1] * inv0);
            *(float2*)&Op[r1l * 64 + col] = make_float2(o[ni][2] * inv1, o[ni][3] * inv1);
        }
    } else {
        const int b = bh >> 3, h = bh & 7;
        float* Op = O + ((long long)b * N_ + blockIdx.x * 64) * DIM_ + h * 64;
#pragma unroll
        for (int ni = 0; ni < 8; ni++) {
            int col = ni * 8 + 2 * tig;
            float2 u0 = *(float2*)&Op[(long long)r0l * DIM_ + col];
            float2 u1 = *(float2*)&Op[(long long)r1l * DIM_ + col];
            u0.x += o[ni][0] * inv0; u0.y += o[ni][1] * inv0;
            u1.x += o[ni][2] * inv1; u1.y += o[ni][3] * inv1;
            *(float2*)&Op[(long long)r0l * DIM_ + col] = u0;
            *(float2*)&Op[(long long)r1l * DIM_ + col] = u1;
        }
    }
}

// ------------------------- landmarks (mean over 16 tokens) -------------------------
__global__ void landmark_kernel(const float* __restrict__ q, const float* __restrict__ k,
                                float* __restrict__ ql, float* __restrict__ kl) {
    int idx = blockIdx.x * 256 + threadIdx.x;      // BH_*M_*DH_ = 524288
    int d = idx & 63;
    int m = (idx >> 6) & 255;
    int bh = idx >> 14;
    long long base = ((long long)bh * N_ + m * 16) * DH_ + d;
    float sq = 0.f, sk = 0.f;
#pragma unroll
    for (int j = 0; j < 16; j++) {
        sq += q[base + (long long)j * DH_];
        sk += k[base + (long long)j * DH_];
    }
    ql[idx] = sq * (1.f / 16.f);
    kl[idx] = sk * (1.f / 16.f);
}

// ------------------------- softmax over last dim (a2 only) -------------------------
__global__ void softmax_kernel(float* __restrict__ p) {
    __shared__ float sh[8];
    float* r = p + (long long)blockIdx.x * 256;
    float v = r[threadIdx.x];
    float mx = blockMax(v, sh, 8);
    float e = expf(v - mx);
    float s = blockSum(e, sh, 8);
    r[threadIdx.x] = e / s;
}

// ------------------------- pinv init helpers -------------------------
// a2 rows are softmax outputs: row sums == 1, so max over dim(-1) sums == 1.
__global__ void init_max_kernel() {
    if (threadIdx.x == 0) g_max = 0u;
}
__global__ void colsum_max_kernel(const float* __restrict__ a2) {
    __shared__ float sh[8];
    int bh = blockIdx.x >> 8, j = blockIdx.x & 255;
    float v = fabsf(a2[(long long)bh * M_ * M_ + (long long)threadIdx.x * M_ + j]);
    float s = blockSum(v, sh, 8);
    if (threadIdx.x == 0) atomicMax(&g_max, __float_as_uint(s));
}
__global__ void zinit_kernel(const float* __restrict__ a2, float* __restrict__ z) {
    int idx = blockIdx.x * 256 + threadIdx.x;       // BH_*M_*M_
    int j = idx & 255, i = (idx >> 8) & 255, bh = idx >> 16;
    float scale = 1.f / __uint_as_float(g_max);
    z[idx] = a2[(long long)bh * M_ * M_ + (long long)j * M_ + i] * scale;
}

// ------------------------- tiled depthwise conv (conv-only, writes outc) ------------
#define VSTR 68
__global__ __launch_bounds__(256) void conv_kernel(
    const float* __restrict__ v, const float* __restrict__ wconv,
    float* __restrict__ outc)
{
    __shared__ float vt[160 * VSTR];
    __shared__ float wc[KC_];
    const int bh = blockIdx.y, h = bh & 7, b = bh >> 3;
    const int n0 = blockIdx.x * 128;
    const int tid = threadIdx.x;
    if (tid < KC_) wc[tid] = wconv[h * KC_ + tid];
    const float* vb = v + (long long)bh * N_ * DH_;
#pragma unroll
    for (int i = 0; i < 10; i++) {
        int idx = tid + i * 256;                    // 2560 float4 slots = 160 rows x 16
        int row = idx >> 4, c4 = (idx & 15) << 2;
        int gn = n0 - 16 + row;
        float4 val = make_float4(0.f, 0.f, 0.f, 0.f);
        if (gn >= 0 && gn < N_) val = *(const float4*)&vb[(long long)gn * DH_ + c4];
        *(float4*)&vt[row * VSTR + c4] = val;
    }
    __syncthreads();
    float* outb = outc + ((long long)b * N_ + n0) * DIM_ + h * DH_;
#pragma unroll 4
    for (int i = 0; i < 32; i++) {
        int idx = tid + i * 256;
        int nl = idx >> 6, d = idx & 63;
        float r = 0.f;
#pragma unroll
        for (int kk = 0; kk < KC_; kk++) r = fmaf(vt[(nl + kk) * VSTR + d], wc[kk], r);
        outb[(long long)nl * DIM_ + d] = r;
    }
}

// ------------------------- host launcher -------------------------
extern "C" void kernel_launch(void* const* d_in, const int* in_sizes, int n_in,
                              void* d_out, int out_size) {
    const float* x      = (const float*)d_in[0];
    const float* ln_w   = (const float*)d_in[1];
    const float* ln_b   = (const float*)d_in[2];
    const float* w_qkv  = (const float*)d_in[3];
    const float* w_out  = (const float*)d_in[4];
    const float* b_out  = (const float*)d_in[5];
    const float* w_conv = (const float*)d_in[6];
    float* out = (float*)d_out;

    float *p_xn, *p_q, *p_k, *p_v, *p_ql, *p_kl, *p_a2;
    float *p_zyA, *p_zyB, *p_p1, *p_t2, *p_a3v, *p_zv, *p_outc;
    cudaGetSymbolAddress((void**)&p_xn,  g_xn);
    cudaGetSymbolAddress((void**)&p_q,   g_q);
    cudaGetSymbolAddress((void**)&p_k,   g_k);
    cudaGetSymbolAddress((void**)&p_v,   g_v);
    cudaGetSymbolAddress((void**)&p_ql,  g_ql);
    cudaGetSymbolAddress((void**)&p_kl,  g_kl);
    cudaGetSymbolAddress((void**)&p_a2,  g_a2);
    cudaGetSymbolAddress((void**)&p_zyA, g_zyA);
    cudaGetSymbolAddress((void**)&p_zyB, g_zyB);
    cudaGetSymbolAddress((void**)&p_p1,  g_p1);
    cudaGetSymbolAddress((void**)&p_t2,  g_t2);
    cudaGetSymbolAddress((void**)&p_a3v, g_a3v);
    cudaGetSymbolAddress((void**)&p_zv,  g_zv);
    cudaGetSymbolAddress((void**)&p_outc,g_outc);

    static cudaStream_t s2 = nullptr;
    static cudaEvent_t evFork = nullptr, evJoin = nullptr;
    static int init_done = 0;
    if (!init_done) {
        cudaFuncSetAttribute(flash_kernel, cudaFuncAttributeMaxDynamicSharedMemorySize, FL_SMEM);
        cudaStreamCreateWithFlags(&s2, cudaStreamNonBlocking);
        cudaEventCreateWithFlags(&evFork, cudaEventDisableTiming);
        cudaEventCreateWithFlags(&evJoin, cudaEventDisableTiming);
        init_done = 1;
    }

    const long long sL  = (long long)M_ * DH_;      // 16384
    const long long sM2 = (long long)M_ * M_;       // 65536

    // 1. LayerNorm
    ln_kernel<<<B_ * N_, 128>>>(x, ln_w, ln_b, p_xn);

    // 2. QKV GEMM [16384,512] @ [512,1536] -> scatter into q/k/v [bh,n,dh]
    mma_gemm<128, 128, 2, 1, false><<<dim3(12, 128, 1), 256>>>(
        p_xn, w_qkv, nullptr, 512, 512, 1536, 0, 0, 0, 0, 1.f, 0.f,
        nullptr, nullptr, p_q, p_k, p_v);

    // 3. Landmarks (mean over 16 tokens)
    landmark_kernel<<<(BH_ * M_ * DH_) / 256, 256>>>(p_q, p_k, p_ql, p_kl);

    // ---- fork: conv + flash3 run concurrently with the sim2/softmax/pinv chain ----
    cudaEventRecord(evFork, 0);
    cudaStreamWaitEvent(s2, evFork, 0);

    // s2: conv(v) -> outc (conv-only part of the residual)
    conv_kernel<<<dim3(N_ / 128, BH_), 256, 0, s2>>>(p_v, w_conv, p_outc);
    // s2: flash3: a3v = softmax(ql @ k^T) @ v   [bh,256,64]
    flash_kernel<<<dim3(M_ / 64, BH_), 128, FL_SMEM, s2>>>(p_ql, p_k, p_v, p_a3v, N_, 0);
    cudaEventRecord(evJoin, s2);

    // main: sim2 = ql @ kl^T [256,256] + softmax
    mma_gemm<128, 128, 2, 0, true><<<dim3(2, 2, BH_), 256>>>(
        p_ql, p_kl, p_a2, 64, 64, 64, 256, sL, sL, sM2, 1.f, 0.f,
        nullptr, nullptr, nullptr, nullptr, nullptr);
    softmax_kernel<<<BH_ * M_, 256>>>(p_a2);

    // pinv init: z0 = a2^T / max(colsums)   (row-sum max == 1, softmaxed rows)
    init_max_kernel<<<1, 32>>>();
    colsum_max_kernel<<<BH_ * M_, 256>>>(p_a2);
    zinit_kernel<<<(BH_ * M_ * M_) / 256, 256>>>(p_a2, p_zyA);

    // y0 = a2 @ z0   (into y half of zyA)
    mma_gemm<128, 128, 2, 0, false><<<dim3(2, 2, BH_), 256>>>(
        p_a2, p_zyA, p_zyA + YOFF_, 256, 256, 256, 256, sM2, sM2, sM2, 1.f, 0.f,
        nullptr, nullptr, nullptr, nullptr, nullptr);

    // Newton-Schulz with y-propagation: 3 GEMMs/iter, last one batched [z,y]
    float* cur = p_zyA;
    float* nxt = p_zyB;
    for (int it = 0; it < ITERS_; it++) {
        float* y = cur + YOFF_;
        // p1 = -y@y + 7y
        mma_gemm<128, 128, 2, 0, false><<<dim3(2, 2, BH_), 256>>>(
            y, y, p_p1, 256, 256, 256, 256, sM2, sM2, sM2, -1.f, 7.f,
            nullptr, nullptr, nullptr, nullptr, nullptr);
        // t2 = -y@p1 + 15y
        mma_gemm<128, 128, 2, 0, false><<<dim3(2, 2, BH_), 256>>>(
            y, p_p1, p_t2, 256, 256, 256, 256, sM2, sM2, sM2, -1.f, 15.f,
            nullptr, nullptr, nullptr, nullptr, nullptr);
        // [z',y'] = -0.25*[z,y]@t2 + 3.25*[z,y]   (batched 64; last iter z only)
        int bz = (it == ITERS_ - 1) ? BH_ : 2 * BH_;
        mma_gemm<128, 128, 2, 0, false, true><<<dim3(2, 2, bz), 256>>>(
            cur, p_t2, nxt, 256, 256, 256, 256, sM2, sM2, sM2, -0.25f, 3.25f,
            nullptr, nullptr, nullptr, nullptr, nullptr);
        float* tmp = cur; cur = nxt; nxt = tmp;
    }

    // ---- join: zv needs pinv result (main) + a3v (s2); flash1 needs conv(outc) ----
    cudaStreamWaitEvent(0, evJoin, 0);

    // zv = a2inv @ a3v  [256,64]
    mma_gemm<128, 64, 4, 0, false><<<dim3(1, 2, BH_), 256>>>(
        cur, p_a3v, p_zv, 256, 256, 64, 64, sM2, sL, sL, 1.f, 0.f,
        nullptr, nullptr, nullptr, nullptr, nullptr);

    // flash1: outc += softmax(q @ kl^T) @ zv   (scatter-accumulate, merged heads)
    flash_kernel<<<dim3(N_ / 64, BH_), 128, FL_SMEM>>>(p_q, p_kl, p_zv, p_outc, M_, 1);

    // final: out = x + outc @ w_out + b_out
    mma_gemm<128, 128, 2, 2, false><<<dim3(4, 128, 1), 256>>>(
        p_outc, w_out, out, 512, 512, 512, 512, 0, 0, 0, 1.f, 0.f,
        x, b_out, nullptr, nullptr, nullptr);
}